// round 14
// baseline (speedup 1.0000x reference)
#include <cuda_runtime.h>
#include <math.h>

#define BLK 64
#define MAXPART 4096
#define NSLOTS 128   // dp slot = mask & 127 (aliasing-safe in ascending order)

__device__ float g_partials[MAXPART];
__device__ unsigned int g_sem;   // zero-init; last block resets each call

__device__ __forceinline__ float fsqrt_fast(float x) {
    float r;
    asm("sqrt.approx.f32 %0, %1;" : "=f"(r) : "f"(x));
    return r;
}

// acos for x in [0,1]: Abramowitz & Stegun 4.4.45, |abs err| <= 6.7e-5 rad
__device__ __forceinline__ float facos01(float x) {
    float s = fsqrt_fast(1.0f - x);
    return s * (1.5707288f + x * (-0.2121144f + x * (0.0742610f + x * (-0.0187293f))));
}

__device__ __forceinline__ void quat_mat(float x, float y, float z, float w,
                                         float eps, float R[3][3]) {
    float n = fsqrt_fast(x*x + y*y + z*z + w*w) + eps;
    float inv = __fdividef(1.0f, n);
    x *= inv; y *= inv; z *= inv; w *= inv;
    R[0][0] = 1.0f - 2.0f*y*y - 2.0f*z*z;
    R[0][1] = 2.0f*x*y - 2.0f*z*w;
    R[0][2] = 2.0f*x*z + 2.0f*y*w;
    R[1][0] = 2.0f*x*y + 2.0f*z*w;
    R[1][1] = 1.0f - 2.0f*x*x - 2.0f*z*z;
    R[1][2] = 2.0f*y*z - 2.0f*x*w;
    R[2][0] = 2.0f*x*z - 2.0f*y*w;
    R[2][1] = 2.0f*y*z + 2.0f*x*w;
    R[2][2] = 1.0f - 2.0f*x*x - 2.0f*y*y;
}

__device__ __forceinline__ float sel3(float a, float b, float c, int k) {
    return (k == 0) ? a : ((k == 1) ? b : c);
}

extern __shared__ float sdp[];

__global__ void __launch_bounds__(BLK, 7)
hybrid_loss_kernel(const float* __restrict__ pred, const float* __restrict__ gt,
                   float* __restrict__ out, int B, float scale) {
    const int tid = threadIdx.x;
    const int b = blockIdx.x * BLK + tid;

    float f = 0.0f;

    if (b < B) {
        float p[10], g[10];
        {   // b*10 floats = b*5 float2, 8-byte aligned
            const float2* pp2 = (const float2*)(pred) + (size_t)b * 5;
            const float2* gp2 = (const float2*)(gt)   + (size_t)b * 5;
#pragma unroll
            for (int i = 0; i < 5; i++) {
                float2 a = pp2[i]; p[2*i] = a.x; p[2*i+1] = a.y;
                float2 c = gp2[i]; g[2*i] = c.x; g[2*i+1] = c.y;
            }
        }

        // ---- diag + center ----
        float gdiag = fsqrt_fast(g[3]*g[3] + g[4]*g[4] + g[5]*g[5]);
        float l_diag = (__fdividef(fabsf(p[3]-g[3]), g[3] + 1e-6f)
                      + __fdividef(fabsf(p[4]-g[4]), g[4] + 1e-6f)
                      + __fdividef(fabsf(p[5]-g[5]), g[5] + 1e-6f)) * (1.0f/3.0f);
        float l_center = __fdividef(fabsf(p[0]-g[0]) + fabsf(p[1]-g[1]) + fabsf(p[2]-g[2]),
                                    gdiag) * (1.0f/3.0f);

        // ---- quat loss (eps 1e-6 normalization); matrices scoped ----
        float l_quat;
        {
            float Rp6[3][3], Rg6[3][3];
            quat_mat(p[6], p[7], p[8], p[9], 1e-6f, Rp6);
            quat_mat(g[6], g[7], g[8], g[9], 1e-6f, Rg6);
            float s = 0.0f;
#pragma unroll
            for (int i = 0; i < 3; i++) {
                float m = 0.0f;
#pragma unroll
                for (int j = 0; j < 3; j++) {
                    float d = Rp6[0][i]*Rg6[0][j] + Rp6[1][i]*Rg6[1][j] + Rp6[2][i]*Rg6[2][j];
                    m = fmaxf(m, fabsf(d));
                }
                m = fminf(fmaxf(m, 1e-6f), 1.0f);
                s += facos01(m);
            }
            l_quat = s * (1.0f/3.0f);
        }

        // ---- rotation matrices with eps 1e-8 (canonical + corners) ----
        float Rp[3][3], Rg[3][3];
        quat_mat(p[6], p[7], p[8], p[9], 1e-8f, Rp);
        quat_mat(g[6], g[7], g[8], g[9], 1e-8f, Rg);

        // ---- canonical loss ----
        float l_canon;
        {
            float pv0 = p[3], pv1 = p[4], pv2 = p[5];
            int   pi0 = 0,    pi1 = 1,    pi2 = 2;
#define CSWAP(va, vb, ia, ib) if ((vb) > (va)) { float _t=(va); (va)=(vb); (vb)=_t; int _i=(ia); (ia)=(ib); (ib)=_i; }
            CSWAP(pv0, pv1, pi0, pi1)
            CSWAP(pv1, pv2, pi1, pi2)
            CSWAP(pv0, pv1, pi0, pi1)
            float gv0 = g[3], gv1 = g[4], gv2 = g[5];
            int   gi0 = 0,    gi1 = 1,    gi2 = 2;
            CSWAP(gv0, gv1, gi0, gi1)
            CSWAP(gv1, gv2, gi1, gi2)
            CSWAP(gv0, gv1, gi0, gi1)
#undef CSWAP
            float dims_loss = (__fdividef(fabsf(pv0-gv0), gv0+1e-8f)
                             + __fdividef(fabsf(pv1-gv1), gv1+1e-8f)
                             + __fdividef(fabsf(pv2-gv2), gv2+1e-8f)) * (1.0f/3.0f);
            int c0 = (gi0 == pi0) ? 0 : ((gi1 == pi0) ? 1 : 2);
            int c1 = (gi0 == pi1) ? 0 : ((gi1 == pi1) ? 1 : 2);
            int c2 = (gi0 == pi2) ? 0 : ((gi1 == pi2) ? 1 : 2);
            float angsum = 0.0f;
#pragma unroll
            for (int i = 0; i < 3; i++) {
                float d = Rp[i][0] * sel3(Rg[i][0], Rg[i][1], Rg[i][2], c0)
                        + Rp[i][1] * sel3(Rg[i][0], Rg[i][1], Rg[i][2], c1)
                        + Rp[i][2] * sel3(Rg[i][0], Rg[i][1], Rg[i][2], c2);
                angsum += facos01(fminf(fabsf(d), 1.0f));
            }
            l_canon = 0.5f * dims_loss + 0.5f * angsum * (1.0f/3.0f);
        }

        // ---- corners + extents ----
        float pcx[8], pcy[8], pcz[8], gcx[8], gcy[8], gcz[8];
        float pmn[3], pmx[3], gmn[3], gmx[3];
#pragma unroll
        for (int k = 0; k < 8; k++) {
            float sx = (k & 4) ? -0.5f : 0.5f;
            float sy = (k & 2) ? -0.5f : 0.5f;
            float sz = (k & 1) ? -0.5f : 0.5f;
            float lx = sx * p[3], ly = sy * p[4], lz = sz * p[5];
            pcx[k] = p[0] + Rp[0][0]*lx + Rp[0][1]*ly + Rp[0][2]*lz;
            pcy[k] = p[1] + Rp[1][0]*lx + Rp[1][1]*ly + Rp[1][2]*lz;
            pcz[k] = p[2] + Rp[2][0]*lx + Rp[2][1]*ly + Rp[2][2]*lz;
            float mx = sx * g[3], my = sy * g[4], mz = sz * g[5];
            gcx[k] = g[0] + Rg[0][0]*mx + Rg[0][1]*my + Rg[0][2]*mz;
            gcy[k] = g[1] + Rg[1][0]*mx + Rg[1][1]*my + Rg[1][2]*mz;
            gcz[k] = g[2] + Rg[2][0]*mx + Rg[2][1]*my + Rg[2][2]*mz;
            if (k == 0) {
                pmn[0] = pmx[0] = pcx[0]; pmn[1] = pmx[1] = pcy[0]; pmn[2] = pmx[2] = pcz[0];
                gmn[0] = gmx[0] = gcx[0]; gmn[1] = gmx[1] = gcy[0]; gmn[2] = gmx[2] = gcz[0];
            } else {
                pmn[0] = fminf(pmn[0], pcx[k]); pmx[0] = fmaxf(pmx[0], pcx[k]);
                pmn[1] = fminf(pmn[1], pcy[k]); pmx[1] = fmaxf(pmx[1], pcy[k]);
                pmn[2] = fminf(pmn[2], pcz[k]); pmx[2] = fmaxf(pmx[2], pcz[k]);
                gmn[0] = fminf(gmn[0], gcx[k]); gmx[0] = fmaxf(gmx[0], gcx[k]);
                gmn[1] = fminf(gmn[1], gcy[k]); gmx[1] = fmaxf(gmx[1], gcy[k]);
                gmn[2] = fminf(gmn[2], gcz[k]); gmx[2] = fmaxf(gmx[2], gcz[k]);
            }
        }

        // ---- projected IoU before the DP (extents die here) ----
        float iou_b;
        {
            const int PA[3] = {0, 0, 1};
            const int PB[3] = {2, 1, 2};
            const int PH[3] = {1, 2, 0};
            float iousum = 0.0f;
#pragma unroll
            for (int t = 0; t < 3; t++) {
                int a = PA[t], bb = PB[t], h = PH[t];
                float ia = fmaxf(fminf(pmx[a],  gmx[a])  - fmaxf(pmn[a],  gmn[a])  + 1e-3f, 0.0f);
                float ib = fmaxf(fminf(pmx[bb], gmx[bb]) - fmaxf(pmn[bb], gmn[bb]) + 1e-3f, 0.0f);
                float inter = ia * ib;
                float a1 = (pmx[a]-pmn[a]+1e-3f) * (pmx[bb]-pmn[bb]+1e-3f);
                float a2 = (gmx[a]-gmn[a]+1e-3f) * (gmx[bb]-gmn[bb]+1e-3f);
                float iou2d = __fdividef(inter, a1 + a2 - inter + 1e-6f);
                float hi = fmaxf(fminf(pmx[h], gmx[h]) - fmaxf(pmn[h], gmn[h]), 0.0f);
                float hu = (pmx[h]-pmn[h]) + (gmx[h]-gmn[h]) - hi;
                iousum += iou2d * __fdividef(hi, hu + 1e-6f);
            }
            iou_b = fminf(fmaxf(iousum * (1.0f/3.0f), 0.0f), 1.0f);
        }

        float f_pre = 0.15f * l_diag + 0.20f * l_center + 0.15f * l_quat
                    + 0.10f * l_canon + 0.20f * (1.0f - iou_b);

        // ---- 8x8 L1 cost matrix in registers (literal indices only) ----
        float cst[64];
#pragma unroll
        for (int r = 0; r < 8; r++) {
#pragma unroll
            for (int j = 0; j < 8; j++) {
                cst[r*8 + j] = fabsf(pcx[r]-gcx[j]) + fabsf(pcy[r]-gcy[j]) + fabsf(pcz[r]-gcz[j]);
            }
        }

        // ====== assignment DP, ascending masks, 128-slot aliased buffer ======
        // slot(mask) = mask & 127. Ascending order is alias-safe (see R6 proof).
        // popc==1 masks: dp = cst row 0 directly (dp[0]==0 never materialized).
        // First candidate assigns best directly (init flag folds at compile time).
        float* dpc = sdp + tid;
        float best = 0.0f;
#pragma unroll
        for (int mask = 1; mask < 256; mask++) {
            const int r = ((mask>>0)&1)+((mask>>1)&1)+((mask>>2)&1)+((mask>>3)&1)
                        + ((mask>>4)&1)+((mask>>5)&1)+((mask>>6)&1)+((mask>>7)&1) - 1;
            bool init = false;
#pragma unroll
            for (int j = 0; j < 8; j++) {
                if (mask & (1 << j)) {
                    float cand;
                    if (r == 0) {
                        cand = cst[j];                       // dp[empty] == 0
                    } else {
                        cand = dpc[((mask ^ (1 << j)) & 127) * BLK] + cst[r*8 + j];
                    }
                    if (!init) { best = cand; init = true; }
                    else       { best = fminf(best, cand); }
                }
            }
            if (mask != 255) dpc[(mask & 127) * BLK] = best;
        }

        f = f_pre + 0.20f * (best * 0.125f * __fdividef(1.0f, gdiag + 1e-6f));
    }

    // ---- deterministic block reduction (smem reuse after DP is dead) ----
    __syncthreads();
    sdp[tid] = f;
    __syncthreads();
#pragma unroll
    for (int s = BLK/2; s > 0; s >>= 1) {
        if (tid < s) sdp[tid] += sdp[tid + s];
        __syncthreads();
    }

    // ---- fused final reduction: last block sums partials in fixed order ----
    if (tid == 0) {
        g_partials[blockIdx.x] = sdp[0];
        __threadfence();
        unsigned int v = atomicAdd(&g_sem, 1u);
        sdp[0] = (v == gridDim.x - 1) ? 1.0f : 0.0f;
    }
    __syncthreads();
    bool last = (sdp[0] != 0.0f);
    __syncthreads();
    if (last) {
        __threadfence();
        float s = 0.0f;
        for (int i = tid; i < (int)gridDim.x; i += BLK) s += g_partials[i];
        sdp[tid] = s;
        __syncthreads();
#pragma unroll
        for (int st = BLK/2; st > 0; st >>= 1) {
            if (tid < st) sdp[tid] += sdp[tid + st];
            __syncthreads();
        }
        if (tid == 0) {
            out[0] = sdp[0] * scale;
            g_sem = 0;   // reset for next graph replay
        }
    }
}

extern "C" void kernel_launch(void* const* d_in, const int* in_sizes, int n_in,
                              void* d_out, int out_size) {
    const float* pred = (const float*)d_in[0];
    const float* gt   = (const float*)d_in[1];
    int B = in_sizes[0] / 10;
    int nblocks = (B + BLK - 1) / BLK;
    if (nblocks > MAXPART) nblocks = MAXPART;  // B=131072 -> 2048 blocks

    size_t smem = (size_t)NSLOTS * BLK * sizeof(float);  // 128*64*4 = 32 KB
    cudaFuncSetAttribute(hybrid_loss_kernel,
                         cudaFuncAttributeMaxDynamicSharedMemorySize, (int)smem);

    hybrid_loss_kernel<<<nblocks, BLK, smem>>>(pred, gt, (float*)d_out, B,
                                               1.0f / (float)B);
}

// round 15
// speedup vs baseline: 1.9783x; 1.9783x over previous
#include <cuda_runtime.h>
#include <math.h>

#define BLK 128
#define MAXPART 4096
#define NSLOTS 128   // dp slot = mask & 127 (aliasing-safe in ascending order)

__device__ float g_partials[MAXPART];
__device__ unsigned int g_sem;   // zero-init; last block resets each call

__device__ __forceinline__ float fsqrt_fast(float x) {
    float r;
    asm("sqrt.approx.f32 %0, %1;" : "=f"(r) : "f"(x));
    return r;
}

// acos for x in [0,1]: Abramowitz & Stegun 4.4.45, |abs err| <= 6.7e-5 rad
__device__ __forceinline__ float facos01(float x) {
    float s = fsqrt_fast(1.0f - x);
    return s * (1.5707288f + x * (-0.2121144f + x * (0.0742610f + x * (-0.0187293f))));
}

__device__ __forceinline__ void quat_mat(float x, float y, float z, float w,
                                         float eps, float R[3][3]) {
    float n = fsqrt_fast(x*x + y*y + z*z + w*w) + eps;
    float inv = __fdividef(1.0f, n);
    x *= inv; y *= inv; z *= inv; w *= inv;
    R[0][0] = 1.0f - 2.0f*y*y - 2.0f*z*z;
    R[0][1] = 2.0f*x*y - 2.0f*z*w;
    R[0][2] = 2.0f*x*z + 2.0f*y*w;
    R[1][0] = 2.0f*x*y + 2.0f*z*w;
    R[1][1] = 1.0f - 2.0f*x*x - 2.0f*z*z;
    R[1][2] = 2.0f*y*z - 2.0f*x*w;
    R[2][0] = 2.0f*x*z - 2.0f*y*w;
    R[2][1] = 2.0f*y*z + 2.0f*x*w;
    R[2][2] = 1.0f - 2.0f*x*x - 2.0f*y*y;
}

__device__ __forceinline__ float sel3(float a, float b, float c, int k) {
    return (k == 0) ? a : ((k == 1) ? b : c);
}

extern __shared__ float sdp[];

__global__ void __launch_bounds__(BLK, 3)
hybrid_loss_kernel(const float* __restrict__ pred, const float* __restrict__ gt,
                   float* __restrict__ out, int B, float scale) {
    const int tid = threadIdx.x;
    const int b = blockIdx.x * BLK + tid;

    float f = 0.0f;

    if (b < B) {
        float p[10], g[10];
        {   // b*10 floats = b*5 float2, 8-byte aligned
            const float2* pp2 = (const float2*)(pred) + (size_t)b * 5;
            const float2* gp2 = (const float2*)(gt)   + (size_t)b * 5;
#pragma unroll
            for (int i = 0; i < 5; i++) {
                float2 a = pp2[i]; p[2*i] = a.x; p[2*i+1] = a.y;
                float2 c = gp2[i]; g[2*i] = c.x; g[2*i+1] = c.y;
            }
        }

        // ---- diag + center ----
        float gdiag = fsqrt_fast(g[3]*g[3] + g[4]*g[4] + g[5]*g[5]);
        float l_diag = (__fdividef(fabsf(p[3]-g[3]), g[3] + 1e-6f)
                      + __fdividef(fabsf(p[4]-g[4]), g[4] + 1e-6f)
                      + __fdividef(fabsf(p[5]-g[5]), g[5] + 1e-6f)) * (1.0f/3.0f);
        float l_center = __fdividef(fabsf(p[0]-g[0]) + fabsf(p[1]-g[1]) + fabsf(p[2]-g[2]),
                                    gdiag) * (1.0f/3.0f);

        // ---- quat loss (eps 1e-6 normalization); matrices scoped ----
        float l_quat;
        {
            float Rp6[3][3], Rg6[3][3];
            quat_mat(p[6], p[7], p[8], p[9], 1e-6f, Rp6);
            quat_mat(g[6], g[7], g[8], g[9], 1e-6f, Rg6);
            float s = 0.0f;
#pragma unroll
            for (int i = 0; i < 3; i++) {
                float m = 0.0f;
#pragma unroll
                for (int j = 0; j < 3; j++) {
                    float d = Rp6[0][i]*Rg6[0][j] + Rp6[1][i]*Rg6[1][j] + Rp6[2][i]*Rg6[2][j];
                    m = fmaxf(m, fabsf(d));
                }
                m = fminf(fmaxf(m, 1e-6f), 1.0f);
                s += facos01(m);
            }
            l_quat = s * (1.0f/3.0f);
        }

        // ---- rotation matrices with eps 1e-8 (canonical + corners) ----
        float Rp[3][3], Rg[3][3];
        quat_mat(p[6], p[7], p[8], p[9], 1e-8f, Rp);
        quat_mat(g[6], g[7], g[8], g[9], 1e-8f, Rg);

        // ---- canonical loss ----
        float l_canon;
        {
            float pv0 = p[3], pv1 = p[4], pv2 = p[5];
            int   pi0 = 0,    pi1 = 1,    pi2 = 2;
#define CSWAP(va, vb, ia, ib) if ((vb) > (va)) { float _t=(va); (va)=(vb); (vb)=_t; int _i=(ia); (ia)=(ib); (ib)=_i; }
            CSWAP(pv0, pv1, pi0, pi1)
            CSWAP(pv1, pv2, pi1, pi2)
            CSWAP(pv0, pv1, pi0, pi1)
            float gv0 = g[3], gv1 = g[4], gv2 = g[5];
            int   gi0 = 0,    gi1 = 1,    gi2 = 2;
            CSWAP(gv0, gv1, gi0, gi1)
            CSWAP(gv1, gv2, gi1, gi2)
            CSWAP(gv0, gv1, gi0, gi1)
#undef CSWAP
            float dims_loss = (__fdividef(fabsf(pv0-gv0), gv0+1e-8f)
                             + __fdividef(fabsf(pv1-gv1), gv1+1e-8f)
                             + __fdividef(fabsf(pv2-gv2), gv2+1e-8f)) * (1.0f/3.0f);
            int c0 = (gi0 == pi0) ? 0 : ((gi1 == pi0) ? 1 : 2);
            int c1 = (gi0 == pi1) ? 0 : ((gi1 == pi1) ? 1 : 2);
            int c2 = (gi0 == pi2) ? 0 : ((gi1 == pi2) ? 1 : 2);
            float angsum = 0.0f;
#pragma unroll
            for (int i = 0; i < 3; i++) {
                float d = Rp[i][0] * sel3(Rg[i][0], Rg[i][1], Rg[i][2], c0)
                        + Rp[i][1] * sel3(Rg[i][0], Rg[i][1], Rg[i][2], c1)
                        + Rp[i][2] * sel3(Rg[i][0], Rg[i][1], Rg[i][2], c2);
                angsum += facos01(fminf(fabsf(d), 1.0f));
            }
            l_canon = 0.5f * dims_loss + 0.5f * angsum * (1.0f/3.0f);
        }

        // ---- corners + extents ----
        float pcx[8], pcy[8], pcz[8], gcx[8], gcy[8], gcz[8];
        float pmn[3], pmx[3], gmn[3], gmx[3];
#pragma unroll
        for (int k = 0; k < 8; k++) {
            float sx = (k & 4) ? -0.5f : 0.5f;
            float sy = (k & 2) ? -0.5f : 0.5f;
            float sz = (k & 1) ? -0.5f : 0.5f;
            float lx = sx * p[3], ly = sy * p[4], lz = sz * p[5];
            pcx[k] = p[0] + Rp[0][0]*lx + Rp[0][1]*ly + Rp[0][2]*lz;
            pcy[k] = p[1] + Rp[1][0]*lx + Rp[1][1]*ly + Rp[1][2]*lz;
            pcz[k] = p[2] + Rp[2][0]*lx + Rp[2][1]*ly + Rp[2][2]*lz;
            float mx = sx * g[3], my = sy * g[4], mz = sz * g[5];
            gcx[k] = g[0] + Rg[0][0]*mx + Rg[0][1]*my + Rg[0][2]*mz;
            gcy[k] = g[1] + Rg[1][0]*mx + Rg[1][1]*my + Rg[1][2]*mz;
            gcz[k] = g[2] + Rg[2][0]*mx + Rg[2][1]*my + Rg[2][2]*mz;
            if (k == 0) {
                pmn[0] = pmx[0] = pcx[0]; pmn[1] = pmx[1] = pcy[0]; pmn[2] = pmx[2] = pcz[0];
                gmn[0] = gmx[0] = gcx[0]; gmn[1] = gmx[1] = gcy[0]; gmn[2] = gmx[2] = gcz[0];
            } else {
                pmn[0] = fminf(pmn[0], pcx[k]); pmx[0] = fmaxf(pmx[0], pcx[k]);
                pmn[1] = fminf(pmn[1], pcy[k]); pmx[1] = fmaxf(pmx[1], pcy[k]);
                pmn[2] = fminf(pmn[2], pcz[k]); pmx[2] = fmaxf(pmx[2], pcz[k]);
                gmn[0] = fminf(gmn[0], gcx[k]); gmx[0] = fmaxf(gmx[0], gcx[k]);
                gmn[1] = fminf(gmn[1], gcy[k]); gmx[1] = fmaxf(gmx[1], gcy[k]);
                gmn[2] = fminf(gmn[2], gcz[k]); gmx[2] = fmaxf(gmx[2], gcz[k]);
            }
        }

        // ---- projected IoU before the DP (extents die here) ----
        float iou_b;
        {
            const int PA[3] = {0, 0, 1};
            const int PB[3] = {2, 1, 2};
            const int PH[3] = {1, 2, 0};
            float iousum = 0.0f;
#pragma unroll
            for (int t = 0; t < 3; t++) {
                int a = PA[t], bb = PB[t], h = PH[t];
                float ia = fmaxf(fminf(pmx[a],  gmx[a])  - fmaxf(pmn[a],  gmn[a])  + 1e-3f, 0.0f);
                float ib = fmaxf(fminf(pmx[bb], gmx[bb]) - fmaxf(pmn[bb], gmn[bb]) + 1e-3f, 0.0f);
                float inter = ia * ib;
                float a1 = (pmx[a]-pmn[a]+1e-3f) * (pmx[bb]-pmn[bb]+1e-3f);
                float a2 = (gmx[a]-gmn[a]+1e-3f) * (gmx[bb]-gmn[bb]+1e-3f);
                float iou2d = __fdividef(inter, a1 + a2 - inter + 1e-6f);
                float hi = fmaxf(fminf(pmx[h], gmx[h]) - fmaxf(pmn[h], gmn[h]), 0.0f);
                float hu = (pmx[h]-pmn[h]) + (gmx[h]-gmn[h]) - hi;
                iousum += iou2d * __fdividef(hi, hu + 1e-6f);
            }
            iou_b = fminf(fmaxf(iousum * (1.0f/3.0f), 0.0f), 1.0f);
        }

        float f_pre = 0.15f * l_diag + 0.20f * l_center + 0.15f * l_quat
                    + 0.10f * l_canon + 0.20f * (1.0f - iou_b);

        // ---- 8x8 L1 cost matrix in registers (literal indices only) ----
        float cst[64];
#pragma unroll
        for (int r = 0; r < 8; r++) {
#pragma unroll
            for (int j = 0; j < 8; j++) {
                cst[r*8 + j] = fabsf(pcx[r]-gcx[j]) + fabsf(pcy[r]-gcy[j]) + fabsf(pcz[r]-gcz[j]);
            }
        }

        // ====== assignment DP, ascending masks, 128-slot aliased buffer ======
        // slot(mask) = mask & 127. Ascending order is alias-safe (see R6 proof).
        // popc==1 masks: dp = cst row 0 directly (dp[0]==0 never materialized).
        // First candidate assigns best directly (init flag folds at compile time).
        float* dpc = sdp + tid;
        float best = 0.0f;
#pragma unroll
        for (int mask = 1; mask < 256; mask++) {
            const int r = ((mask>>0)&1)+((mask>>1)&1)+((mask>>2)&1)+((mask>>3)&1)
                        + ((mask>>4)&1)+((mask>>5)&1)+((mask>>6)&1)+((mask>>7)&1) - 1;
            bool init = false;
#pragma unroll
            for (int j = 0; j < 8; j++) {
                if (mask & (1 << j)) {
                    float cand;
                    if (r == 0) {
                        cand = cst[j];                       // dp[empty] == 0
                    } else {
                        cand = dpc[((mask ^ (1 << j)) & 127) * BLK] + cst[r*8 + j];
                    }
                    if (!init) { best = cand; init = true; }
                    else       { best = fminf(best, cand); }
                }
            }
            if (mask != 255) dpc[(mask & 127) * BLK] = best;
        }

        f = f_pre + 0.20f * (best * 0.125f * __fdividef(1.0f, gdiag + 1e-6f));
    }

    // ---- deterministic block reduction (smem reuse after DP is dead) ----
    __syncthreads();
    sdp[tid] = f;
    __syncthreads();
#pragma unroll
    for (int s = BLK/2; s > 0; s >>= 1) {
        if (tid < s) sdp[tid] += sdp[tid + s];
        __syncthreads();
    }

    // ---- fused final reduction: last block sums partials in fixed order ----
    if (tid == 0) {
        g_partials[blockIdx.x] = sdp[0];
        __threadfence();
        unsigned int v = atomicAdd(&g_sem, 1u);
        sdp[0] = (v == gridDim.x - 1) ? 1.0f : 0.0f;
    }
    __syncthreads();
    bool last = (sdp[0] != 0.0f);
    __syncthreads();
    if (last) {
        __threadfence();
        float s = 0.0f;
        for (int i = tid; i < (int)gridDim.x; i += BLK) s += g_partials[i];
        sdp[tid] = s;
        __syncthreads();
#pragma unroll
        for (int st = BLK/2; st > 0; st >>= 1) {
            if (tid < st) sdp[tid] += sdp[tid + st];
            __syncthreads();
        }
        if (tid == 0) {
            out[0] = sdp[0] * scale;
            g_sem = 0;   // reset for next graph replay
        }
    }
}

extern "C" void kernel_launch(void* const* d_in, const int* in_sizes, int n_in,
                              void* d_out, int out_size) {
    const float* pred = (const float*)d_in[0];
    const float* gt   = (const float*)d_in[1];
    int B = in_sizes[0] / 10;
    int nblocks = (B + BLK - 1) / BLK;
    if (nblocks > MAXPART) nblocks = MAXPART;  // B=131072 -> 1024 blocks

    size_t smem = (size_t)NSLOTS * BLK * sizeof(float);  // 128*128*4 = 64 KB
    cudaFuncSetAttribute(hybrid_loss_kernel,
                         cudaFuncAttributeMaxDynamicSharedMemorySize, (int)smem);

    hybrid_loss_kernel<<<nblocks, BLK, smem>>>(pred, gt, (float*)d_out, B,
                                               1.0f / (float)B);
}